// round 14
// baseline (speedup 1.0000x reference)
#include <cuda_runtime.h>

// FFJORD: 2 chained fixed-step DOPRI5 integrations of a (64+1)->256->256->64 MLP.
// One CTA integrates 16 batch rows. fp32 via fma.rn.f32x2.
// R14 = R13 + (a) t-column folded into layer-1 bias (K=65 -> 64, no t-row),
//             (b) cross-layer prefetch.global.L1 of the next dense's first
//                 ring rows in each epilogue (hides dense-prologue L2 latency).

typedef unsigned long long u64;

#define Dd     64
#define Hh     256
#define MROWS  16
#define STRA   20      // plain activation stride (floats, 80B rows)
#define STRY   16
#define NT     128
#define NSTEPS 16
#define NCTAS  (4096 / MROWS)   // 256
#define RD     8       // weight prefetch ring depth

// smem: sZ[Dd][STRA] + sH1[Hh][STRA] + sH2[Hh][STRA] + sY[Dd][STRY] + sK[6][Dd][STRA]
#define SM_FLOATS ((Dd + Hh + Hh + 6*Dd) * STRA + Dd * STRY)
#define SM_BYTES  (SM_FLOATS * 4)    // ~80.9 KB -> 2 CTAs/SM

struct FfjordParams {
    const float* W1[2]; const float* b1[2];
    const float* W2[2]; const float* b2[2];
    const float* W3[2]; const float* b3[2];
};

__device__ __forceinline__ u64 dup2(float v) {
    u64 r; asm("mov.b64 %0, {%1, %1};" : "=l"(r) : "r"(__float_as_uint(v)));
    return r;
}
__device__ __forceinline__ void fma2(u64& d, u64 a, u64 b) {
    asm("fma.rn.f32x2 %0, %1, %2, %3;" : "=l"(d) : "l"(a), "l"(b), "l"(d));
}
__device__ __forceinline__ float lo32(u64 v){ return __uint_as_float((unsigned)v); }
__device__ __forceinline__ float hi32(u64 v){ return __uint_as_float((unsigned)(v>>32)); }

__device__ __forceinline__ float4 ldg4(const float* p) {
    float4 v;
    asm("ld.global.nc.v4.f32 {%0,%1,%2,%3}, [%4];"
        : "=f"(v.x), "=f"(v.y), "=f"(v.z), "=f"(v.w) : "l"(p));
    return v;
}
__device__ __forceinline__ float2 ldg2f(const float* p) {
    float2 v;
    asm("ld.global.nc.v2.f32 {%0,%1}, [%2];" : "=f"(v.x), "=f"(v.y) : "l"(p));
    return v;
}
__device__ __forceinline__ void pf_l1(const float* p) {
    asm volatile("prefetch.global.L1 [%0];" :: "l"(p));
}

// single-MUFU tanh (sm_75+): max rel err ~5e-4
__device__ __forceinline__ float fast_tanh(float x) {
    float r; asm("tanh.approx.f32 %0, %1;" : "=f"(r) : "f"(x)); return r;
}

__device__ __forceinline__ float4 f4_fma(float c, float4 a, float4 acc) {
    return make_float4(fmaf(c, a.x, acc.x), fmaf(c, a.y, acc.y),
                       fmaf(c, a.z, acc.z), fmaf(c, a.w, acc.w));
}

__constant__ float DP_A[6][5] = {
    { 0.f, 0.f, 0.f, 0.f, 0.f },
    { 1.f/5.f, 0.f, 0.f, 0.f, 0.f },
    { 3.f/40.f, 9.f/40.f, 0.f, 0.f, 0.f },
    { 44.f/45.f, -56.f/15.f, 32.f/9.f, 0.f, 0.f },
    { 19372.f/6561.f, -25360.f/2187.f, 64448.f/6561.f, -212.f/729.f, 0.f },
    { 9017.f/3168.f, -355.f/33.f, 46732.f/5247.f, 49.f/176.f, -5103.f/18656.f },
};
__constant__ float DP_C[6] = { 0.f, 1.f/5.f, 3.f/10.f, 4.f/5.f, 8.f/9.f, 1.f };
__constant__ float DP_B[6] = { 35.f/384.f, 0.f, 500.f/1113.f, 125.f/192.f,
                               -2187.f/6784.f, 11.f/84.f };

// N=256 layer. 4 warps: rowgroup rg=w&1 (rows 8*rg..+7), colgroup g=w>>1
// (cols 128*g + 4*lane..+3). Row-pair accumulators; dist-2 act prefetch.
// TFOLD: bias' = bias + t * tw (time column folded into bias).
// pf/pfStride: epilogue prefetch of next dense's first RD weight rows.
template<int K, bool TANH, bool TFOLD>
__device__ __forceinline__ void dense256(
    const float* __restrict__ W, const float* __restrict__ bias,
    const float* __restrict__ tw, float t,
    const float* __restrict__ sA, float* __restrict__ sOut,
    const float* __restrict__ pf, int pfStride,
    int lane, int g, int r0)
{
    u64 acc[4][4];
    {
        float4 b = *(const float4*)(bias + 128*g + 4*lane);
        if (TFOLD) {
            float4 wt = ldg4(tw + 128*g + 4*lane);
            b.x = fmaf(t, wt.x, b.x); b.y = fmaf(t, wt.y, b.y);
            b.z = fmaf(t, wt.z, b.z); b.w = fmaf(t, wt.w, b.w);
        }
        u64 b0 = dup2(b.x), b1 = dup2(b.y), b2 = dup2(b.z), b3 = dup2(b.w);
#pragma unroll
        for (int q = 0; q < 4; q++) {
            acc[q][0] = b0; acc[q][1] = b1; acc[q][2] = b2; acc[q][3] = b3;
        }
    }

    const float* w0 = W + 128*g + 4*lane;
    const float* aP = sA + r0;

    float4 wb[RD];
#pragma unroll
    for (int s = 0; s < RD; s++) wb[s] = ldg4(w0 + s*Hh);

    u64 ab[2][4];                      // dist-2 act prefetch
#pragma unroll
    for (int s = 0; s < 2; s++) {
        ulonglong2 t0 = *(const ulonglong2*)(aP + s*STRA);
        ulonglong2 t1 = *(const ulonglong2*)(aP + s*STRA + 4);
        ab[s][0] = t0.x; ab[s][1] = t0.y; ab[s][2] = t1.x; ab[s][3] = t1.y;
    }

    int k = 0;
#pragma unroll 8
    for (; k < K - RD; k++) {
        const int slot = k & (RD-1), pb = k & 1;
        float4 wf = wb[slot];
        wb[slot] = ldg4(w0 + (k + RD)*Hh);
        u64 a0 = ab[pb][0], a1 = ab[pb][1], a2 = ab[pb][2], a3 = ab[pb][3];
        {
            const float* ap2 = aP + (k+2)*STRA;
            ulonglong2 t0 = *(const ulonglong2*)(ap2);
            ulonglong2 t1 = *(const ulonglong2*)(ap2 + 4);
            ab[pb][0] = t0.x; ab[pb][1] = t0.y;
            ab[pb][2] = t1.x; ab[pb][3] = t1.y;
        }
        u64 wA = dup2(wf.x), wB = dup2(wf.y), wC = dup2(wf.z), wD = dup2(wf.w);
        fma2(acc[0][0], a0, wA); fma2(acc[0][1], a0, wB);
        fma2(acc[0][2], a0, wC); fma2(acc[0][3], a0, wD);
        fma2(acc[1][0], a1, wA); fma2(acc[1][1], a1, wB);
        fma2(acc[1][2], a1, wC); fma2(acc[1][3], a1, wD);
        fma2(acc[2][0], a2, wA); fma2(acc[2][1], a2, wB);
        fma2(acc[2][2], a2, wC); fma2(acc[2][3], a2, wD);
        fma2(acc[3][0], a3, wA); fma2(acc[3][1], a3, wB);
        fma2(acc[3][2], a3, wC); fma2(acc[3][3], a3, wD);
    }
#pragma unroll
    for (; k < K; k++) {               // tail: ring holds k..K-1
        const int slot = k & (RD-1), pb = k & 1;
        float4 wf = wb[slot];
        u64 a0 = ab[pb][0], a1 = ab[pb][1], a2 = ab[pb][2], a3 = ab[pb][3];
        if (k + 2 < K) {
            const float* ap2 = aP + (k+2)*STRA;
            ulonglong2 t0 = *(const ulonglong2*)(ap2);
            ulonglong2 t1 = *(const ulonglong2*)(ap2 + 4);
            ab[pb][0] = t0.x; ab[pb][1] = t0.y;
            ab[pb][2] = t1.x; ab[pb][3] = t1.y;
        }
        u64 wA = dup2(wf.x), wB = dup2(wf.y), wC = dup2(wf.z), wD = dup2(wf.w);
        fma2(acc[0][0], a0, wA); fma2(acc[0][1], a0, wB);
        fma2(acc[0][2], a0, wC); fma2(acc[0][3], a0, wD);
        fma2(acc[1][0], a1, wA); fma2(acc[1][1], a1, wB);
        fma2(acc[1][2], a1, wC); fma2(acc[1][3], a1, wD);
        fma2(acc[2][0], a2, wA); fma2(acc[2][1], a2, wB);
        fma2(acc[2][2], a2, wC); fma2(acc[2][3], a2, wD);
        fma2(acc[3][0], a3, wA); fma2(acc[3][1], a3, wB);
        fma2(acc[3][2], a3, wC); fma2(acc[3][3], a3, wD);
    }

    // prefetch next dense's first ring rows into L1 (register-free)
#pragma unroll
    for (int s = 0; s < RD; s++) pf_l1(pf + s*pfStride);

    const int rot = (lane >> 1) & 3;
#pragma unroll
    for (int cc = 0; cc < 4; cc++) {
        int c = (cc + rot) & 3;
        float v[8];
#pragma unroll
        for (int q = 0; q < 4; q++) {
            v[2*q]   = lo32(acc[q][c]);
            v[2*q+1] = hi32(acc[q][c]);
        }
        if (TANH) {
#pragma unroll
            for (int r = 0; r < 8; r++) v[r] = fast_tanh(v[r]);
        }
        float* o = sOut + (128*g + 4*lane + c)*STRA + r0;
        *(float4*)(o)     = make_float4(v[0], v[1], v[2], v[3]);
        *(float4*)(o + 4) = make_float4(v[4], v[5], v[6], v[7]);
    }
}

// N=64 output layer with FUSED stage glue. No t-row (folded into L1 bias).
__device__ __forceinline__ void dense64_fused(
    const float* __restrict__ W, const float* __restrict__ bias,
    const float* __restrict__ sA, float* __restrict__ sK,
    float* __restrict__ sY, float* __restrict__ sZ,
    const float cf[5], float cfr, int s, bool writeY,
    const float* __restrict__ pf, int pfStride,
    int lane, int r0d)
{
    u64 acc[2][2];
    {
        float2 bb = *(const float2*)(bias + 2*lane);
        u64 b0 = dup2(bb.x), b1 = dup2(bb.y);
        acc[0][0] = b0; acc[1][0] = b0;
        acc[0][1] = b1; acc[1][1] = b1;
    }
    const float* w0 = W + 2*lane;
    const float* aP = sA + r0d;

    float2 wb[RD];
#pragma unroll
    for (int q = 0; q < RD; q++) wb[q] = ldg2f(w0 + q*Dd);
    u64 ab[2][2];
#pragma unroll
    for (int q = 0; q < 2; q++) {
        ulonglong2 t = *(const ulonglong2*)(aP + q*STRA);
        ab[q][0] = t.x; ab[q][1] = t.y;
    }

    int k = 0;
#pragma unroll 8
    for (; k < Hh - RD; k++) {
        const int slot = k & (RD-1), pb = k & 1;
        float2 wf = wb[slot];
        wb[slot] = ldg2f(w0 + (k + RD)*Dd);
        u64 a0 = ab[pb][0], a1 = ab[pb][1];
        {
            ulonglong2 t = *(const ulonglong2*)(aP + (k+2)*STRA);
            ab[pb][0] = t.x; ab[pb][1] = t.y;
        }
        u64 wA = dup2(wf.x), wB = dup2(wf.y);
        fma2(acc[0][0], a0, wA); fma2(acc[1][0], a1, wA);
        fma2(acc[0][1], a0, wB); fma2(acc[1][1], a1, wB);
    }
#pragma unroll
    for (; k < Hh; k++) {
        const int slot = k & (RD-1), pb = k & 1;
        float2 wf = wb[slot];
        u64 a0 = ab[pb][0], a1 = ab[pb][1];
        if (k + 2 < Hh) {
            ulonglong2 t = *(const ulonglong2*)(aP + (k+2)*STRA);
            ab[pb][0] = t.x; ab[pb][1] = t.y;
        }
        u64 wA = dup2(wf.x), wB = dup2(wf.y);
        fma2(acc[0][0], a0, wA); fma2(acc[1][0], a1, wA);
        fma2(acc[0][1], a0, wB); fma2(acc[1][1], a1, wB);
    }

#pragma unroll
    for (int q = 0; q < RD; q++) pf_l1(pf + q*pfStride);

    const int c0 = 2*lane, c1 = 2*lane + 1;
    float4 v0 = make_float4(lo32(acc[0][0]), hi32(acc[0][0]),
                            lo32(acc[1][0]), hi32(acc[1][0]));
    float4 v1 = make_float4(lo32(acc[0][1]), hi32(acc[0][1]),
                            lo32(acc[1][1]), hi32(acc[1][1]));

    if (s < 5) {
        float* kd = sK + s * Dd * STRA;
        float* p0 = kd + c0*STRA + r0d;
        float* p1 = kd + c1*STRA + r0d;
        if ((lane >> 1) & 1) { *(float4*)p1 = v1; *(float4*)p0 = v0; }
        else                 { *(float4*)p0 = v0; *(float4*)p1 = v1; }
    }

    float4 z0 = *(const float4*)(sY + c0*STRY + r0d);
    float4 z1 = *(const float4*)(sY + c1*STRY + r0d);
    z0 = f4_fma(cfr, v0, z0);
    z1 = f4_fma(cfr, v1, z1);
#pragma unroll
    for (int l = 0; l < 5; l++) {
        if (l < s) {
            const float* kb = sK + l * Dd * STRA;
            float4 k0 = *(const float4*)(kb + c0*STRA + r0d);
            float4 k1 = *(const float4*)(kb + c1*STRA + r0d);
            z0 = f4_fma(cf[l], k0, z0);
            z1 = f4_fma(cf[l], k1, z1);
        }
    }
    *(float4*)(sZ + c0*STRA + r0d) = z0;
    *(float4*)(sZ + c1*STRA + r0d) = z1;
    if (writeY) {
        *(float4*)(sY + c0*STRY + r0d) = z0;
        *(float4*)(sY + c1*STRY + r0d) = z1;
    }
}

__global__ void __launch_bounds__(NT, 2)
ffjord_kernel(const float* __restrict__ x, float* __restrict__ out, FfjordParams P)
{
    extern __shared__ float sm[];
    float* sZ   = sm;                          // Dd x STRA (no t-row)
    float* sH1  = sZ + Dd * STRA;              // Hh x STRA
    float* sH2  = sH1 + Hh * STRA;             // Hh x STRA
    float* sY   = sH2 + Hh * STRA;             // Dd x STRY
    float* sK   = sY + Dd * STRY;              // [6][Dd][STRA] (slot 5 unused)

    const int tid   = threadIdx.x;
    const int lane  = tid & 31;
    const int w     = tid >> 5;
    const int r0    = (w & 1) * 8;
    const int g     = w >> 1;
    const int r0d   = w * 4;
    const int rbase = blockIdx.x * MROWS;

    for (int i = tid; i < MROWS * Dd; i += NT) {
        int r = i >> 6, d = i & 63;
        float v = x[(rbase + r) * Dd + d];
        sY[d * STRY + r] = v;
        sZ[d * STRA + r] = v;
    }
    __syncthreads();

    const float h = 1.0f / 16.0f;

    for (int bij = 0; bij < 2; bij++) {
        const float* W1 = P.W1[bij]; const float* b1 = P.b1[bij];
        const float* W2 = P.W2[bij]; const float* b2 = P.b2[bij];
        const float* W3 = P.W3[bij]; const float* b3 = P.b3[bij];
        const float* W1t = W1 + Dd * Hh;           // time row (row 64)
        const float* pf1 = W2 + 128*g + 4*lane;    // next after L1: W2 slice
        const float* pf2 = W3 + 2*lane;            // next after L2: W3 slice
        const float* pf3 = W1 + 128*g + 4*lane;    // next after dense64: W1 slice

        for (int step = 0; step < NSTEPS; step++) {
            float t0 = (float)step * h;

            for (int s = 0; s < 6; s++) {
                float tstage = t0 + DP_C[s] * h;

                dense256<Dd, true, true >(W1, b1, W1t, tstage, sZ, sH1,
                                          pf1, Hh, lane, g, r0);
                __syncthreads();
                dense256<Hh, true, false>(W2, b2, nullptr, 0.f, sH1, sH2,
                                          pf2, Dd, lane, g, r0);
                __syncthreads();

                float cf[5], cfr;
                bool writeY = (s == 5);
                if (s < 5) {
#pragma unroll
                    for (int l = 0; l < 5; l++) cf[l] = h * DP_A[s+1][l];
                    cfr = h * DP_A[s+1][s];
                } else {
#pragma unroll
                    for (int l = 0; l < 5; l++) cf[l] = h * DP_B[l];
                    cfr = h * DP_B[5];
                }
                dense64_fused(W3, b3, sH2, sK, sY, sZ,
                              cf, cfr, s, writeY, pf3, Hh, lane, r0d);
                __syncthreads();
            }
        }
    }

    for (int i = tid; i < MROWS * Dd; i += NT) {
        int r = i >> 6, d = i & 63;
        out[(rbase + r) * Dd + d] = sY[d * STRY + r];
    }
}

extern "C" void kernel_launch(void* const* d_in, const int* in_sizes, int n_in,
                              void* d_out, int out_size)
{
    (void)in_sizes; (void)n_in; (void)out_size;
    const float* x = (const float*)d_in[0];

    FfjordParams P;
    P.W1[0] = (const float*)d_in[1];  P.b1[0] = (const float*)d_in[2];
    P.W2[0] = (const float*)d_in[3];  P.b2[0] = (const float*)d_in[4];
    P.W3[0] = (const float*)d_in[5];  P.b3[0] = (const float*)d_in[6];
    P.W1[1] = (const float*)d_in[7];  P.b1[1] = (const float*)d_in[8];
    P.W2[1] = (const float*)d_in[9];  P.b2[1] = (const float*)d_in[10];
    P.W3[1] = (const float*)d_in[11]; P.b3[1] = (const float*)d_in[12];

    static_assert(SM_BYTES <= 100 * 1024, "smem budget (2 CTAs/SM)");
    cudaFuncSetAttribute(ffjord_kernel, cudaFuncAttributeMaxDynamicSharedMemorySize, SM_BYTES);

    ffjord_kernel<<<NCTAS, NT, SM_BYTES>>>(x, (float*)d_out, P);
}

// round 15
// speedup vs baseline: 1.1092x; 1.1092x over previous
#include <cuda_runtime.h>

// FFJORD: 2 chained fixed-step DOPRI5 integrations of a (64+1)->256->256->64 MLP.
// One CTA integrates 16 batch rows. fp32 via fma.rn.f32x2.
// R15 = R13 (best) + t-fold (K=65->64, no t-row; prefetch from R14 REVERTED)
//      + split-K dense64: it was issue-bound (10 instr / 4 fma2); now each
//        thread does 2 cols x 8 rows over half of K (16 instr / 8 fma2,
//        FMA-bound), f32x2 partials reduced via smem + add.rn.f32x2.

typedef unsigned long long u64;

#define Dd     64
#define Hh     256
#define MROWS  16
#define STRA   20      // plain activation stride (floats, 80B rows)
#define STRY   16
#define NT     128
#define NSTEPS 16
#define NCTAS  (4096 / MROWS)   // 256
#define RD     8       // weight prefetch ring depth

// smem: sZ[Dd][STRA] + sH1[Hh][STRA] + sH2[Hh][STRA] + sY[Dd][STRY]
//       + sK[6][Dd][STRA] + sPart[4*64 ulonglong2]
#define SM_FLOATS ((Dd + Hh + Hh + 6*Dd) * STRA + Dd * STRY)
#define SM_BYTES  (SM_FLOATS * 4 + 4 * 64 * 16)   // ~84.9 KB -> 2 CTAs/SM

struct FfjordParams {
    const float* W1[2]; const float* b1[2];
    const float* W2[2]; const float* b2[2];
    const float* W3[2]; const float* b3[2];
};

__device__ __forceinline__ u64 dup2(float v) {
    u64 r; asm("mov.b64 %0, {%1, %1};" : "=l"(r) : "r"(__float_as_uint(v)));
    return r;
}
__device__ __forceinline__ void fma2(u64& d, u64 a, u64 b) {
    asm("fma.rn.f32x2 %0, %1, %2, %3;" : "=l"(d) : "l"(a), "l"(b), "l"(d));
}
__device__ __forceinline__ u64 add2(u64 a, u64 b) {
    u64 r; asm("add.rn.f32x2 %0, %1, %2;" : "=l"(r) : "l"(a), "l"(b)); return r;
}
__device__ __forceinline__ float lo32(u64 v){ return __uint_as_float((unsigned)v); }
__device__ __forceinline__ float hi32(u64 v){ return __uint_as_float((unsigned)(v>>32)); }

__device__ __forceinline__ float4 ldg4(const float* p) {
    float4 v;
    asm("ld.global.nc.v4.f32 {%0,%1,%2,%3}, [%4];"
        : "=f"(v.x), "=f"(v.y), "=f"(v.z), "=f"(v.w) : "l"(p));
    return v;
}
__device__ __forceinline__ float2 ldg2f(const float* p) {
    float2 v;
    asm("ld.global.nc.v2.f32 {%0,%1}, [%2];" : "=f"(v.x), "=f"(v.y) : "l"(p));
    return v;
}

// single-MUFU tanh (sm_75+): max rel err ~5e-4
__device__ __forceinline__ float fast_tanh(float x) {
    float r; asm("tanh.approx.f32 %0, %1;" : "=f"(r) : "f"(x)); return r;
}

__device__ __forceinline__ float4 f4_fma(float c, float4 a, float4 acc) {
    return make_float4(fmaf(c, a.x, acc.x), fmaf(c, a.y, acc.y),
                       fmaf(c, a.z, acc.z), fmaf(c, a.w, acc.w));
}

__constant__ float DP_A[6][5] = {
    { 0.f, 0.f, 0.f, 0.f, 0.f },
    { 1.f/5.f, 0.f, 0.f, 0.f, 0.f },
    { 3.f/40.f, 9.f/40.f, 0.f, 0.f, 0.f },
    { 44.f/45.f, -56.f/15.f, 32.f/9.f, 0.f, 0.f },
    { 19372.f/6561.f, -25360.f/2187.f, 64448.f/6561.f, -212.f/729.f, 0.f },
    { 9017.f/3168.f, -355.f/33.f, 46732.f/5247.f, 49.f/176.f, -5103.f/18656.f },
};
__constant__ float DP_C[6] = { 0.f, 1.f/5.f, 3.f/10.f, 4.f/5.f, 8.f/9.f, 1.f };
__constant__ float DP_B[6] = { 35.f/384.f, 0.f, 500.f/1113.f, 125.f/192.f,
                               -2187.f/6784.f, 11.f/84.f };

// N=256 layer. 4 warps: rowgroup rg=w&1 (rows 8*rg..+7), colgroup g=w>>1
// (cols 128*g + 4*lane..+3). Row-pair accumulators; dist-2 act prefetch.
// TFOLD: bias' = bias + t * tw (time column folded into bias).
template<int K, bool TANH, bool TFOLD>
__device__ __forceinline__ void dense256(
    const float* __restrict__ W, const float* __restrict__ bias,
    const float* __restrict__ tw, float t,
    const float* __restrict__ sA, float* __restrict__ sOut,
    int lane, int g, int r0)
{
    u64 acc[4][4];
    {
        float4 b = *(const float4*)(bias + 128*g + 4*lane);
        if (TFOLD) {
            float4 wt = ldg4(tw + 128*g + 4*lane);
            b.x = fmaf(t, wt.x, b.x); b.y = fmaf(t, wt.y, b.y);
            b.z = fmaf(t, wt.z, b.z); b.w = fmaf(t, wt.w, b.w);
        }
        u64 b0 = dup2(b.x), b1 = dup2(b.y), b2 = dup2(b.z), b3 = dup2(b.w);
#pragma unroll
        for (int q = 0; q < 4; q++) {
            acc[q][0] = b0; acc[q][1] = b1; acc[q][2] = b2; acc[q][3] = b3;
        }
    }

    const float* w0 = W + 128*g + 4*lane;
    const float* aP = sA + r0;

    float4 wb[RD];
#pragma unroll
    for (int s = 0; s < RD; s++) wb[s] = ldg4(w0 + s*Hh);

    u64 ab[2][4];                      // dist-2 act prefetch
#pragma unroll
    for (int s = 0; s < 2; s++) {
        ulonglong2 t0 = *(const ulonglong2*)(aP + s*STRA);
        ulonglong2 t1 = *(const ulonglong2*)(aP + s*STRA + 4);
        ab[s][0] = t0.x; ab[s][1] = t0.y; ab[s][2] = t1.x; ab[s][3] = t1.y;
    }

    int k = 0;
#pragma unroll 8
    for (; k < K - RD; k++) {
        const int slot = k & (RD-1), pb = k & 1;
        float4 wf = wb[slot];
        wb[slot] = ldg4(w0 + (k + RD)*Hh);
        u64 a0 = ab[pb][0], a1 = ab[pb][1], a2 = ab[pb][2], a3 = ab[pb][3];
        {
            const float* ap2 = aP + (k+2)*STRA;
            ulonglong2 t0 = *(const ulonglong2*)(ap2);
            ulonglong2 t1 = *(const ulonglong2*)(ap2 + 4);
            ab[pb][0] = t0.x; ab[pb][1] = t0.y;
            ab[pb][2] = t1.x; ab[pb][3] = t1.y;
        }
        u64 wA = dup2(wf.x), wB = dup2(wf.y), wC = dup2(wf.z), wD = dup2(wf.w);
        fma2(acc[0][0], a0, wA); fma2(acc[0][1], a0, wB);
        fma2(acc[0][2], a0, wC); fma2(acc[0][3], a0, wD);
        fma2(acc[1][0], a1, wA); fma2(acc[1][1], a1, wB);
        fma2(acc[1][2], a1, wC); fma2(acc[1][3], a1, wD);
        fma2(acc[2][0], a2, wA); fma2(acc[2][1], a2, wB);
        fma2(acc[2][2], a2, wC); fma2(acc[2][3], a2, wD);
        fma2(acc[3][0], a3, wA); fma2(acc[3][1], a3, wB);
        fma2(acc[3][2], a3, wC); fma2(acc[3][3], a3, wD);
    }
#pragma unroll
    for (; k < K; k++) {               // tail: ring holds k..K-1
        const int slot = k & (RD-1), pb = k & 1;
        float4 wf = wb[slot];
        u64 a0 = ab[pb][0], a1 = ab[pb][1], a2 = ab[pb][2], a3 = ab[pb][3];
        if (k + 2 < K) {
            const float* ap2 = aP + (k+2)*STRA;
            ulonglong2 t0 = *(const ulonglong2*)(ap2);
            ulonglong2 t1 = *(const ulonglong2*)(ap2 + 4);
            ab[pb][0] = t0.x; ab[pb][1] = t0.y;
            ab[pb][2] = t1.x; ab[pb][3] = t1.y;
        }
        u64 wA = dup2(wf.x), wB = dup2(wf.y), wC = dup2(wf.z), wD = dup2(wf.w);
        fma2(acc[0][0], a0, wA); fma2(acc[0][1], a0, wB);
        fma2(acc[0][2], a0, wC); fma2(acc[0][3], a0, wD);
        fma2(acc[1][0], a1, wA); fma2(acc[1][1], a1, wB);
        fma2(acc[1][2], a1, wC); fma2(acc[1][3], a1, wD);
        fma2(acc[2][0], a2, wA); fma2(acc[2][1], a2, wB);
        fma2(acc[2][2], a2, wC); fma2(acc[2][3], a2, wD);
        fma2(acc[3][0], a3, wA); fma2(acc[3][1], a3, wB);
        fma2(acc[3][2], a3, wC); fma2(acc[3][3], a3, wD);
    }

    const int rot = (lane >> 1) & 3;
#pragma unroll
    for (int cc = 0; cc < 4; cc++) {
        int c = (cc + rot) & 3;
        float v[8];
#pragma unroll
        for (int q = 0; q < 4; q++) {
            v[2*q]   = lo32(acc[q][c]);
            v[2*q+1] = hi32(acc[q][c]);
        }
        if (TANH) {
#pragma unroll
            for (int r = 0; r < 8; r++) v[r] = fast_tanh(v[r]);
        }
        float* o = sOut + (128*g + 4*lane + c)*STRA + r0;
        *(float4*)(o)     = make_float4(v[0], v[1], v[2], v[3]);
        *(float4*)(o + 4) = make_float4(v[4], v[5], v[6], v[7]);
    }
}

// N=64 output layer (K=256), SPLIT-K + fused RK glue.
// Warp w: rg=w&1 -> rows 8*rg..+7; kg=w>>1 -> k in [128*kg, 128*kg+128).
// Thread: cols (2*lane, 2*lane+1) x 8 rows; acc[q][c] = rows (2q,2q+1).
// kg1 stores f32x2 partials to sPart ([j][thread] layout, conflict-free);
// kg0 reduces with add.rn.f32x2, then does k-store + Z/y glue for its 8 rows.
// Contains ONE internal __syncthreads (all threads reach it).
__device__ __forceinline__ void dense64_splitk_fused(
    const float* __restrict__ W, const float* __restrict__ bias,
    const float* __restrict__ sA, float* __restrict__ sK,
    float* __restrict__ sY, float* __restrict__ sZ,
    ulonglong2* __restrict__ sPart,
    const float cf[5], float cfr, int s, bool writeY,
    int lane, int rg, int kg)
{
    const int r0d = rg * 8;
    u64 acc[4][2];
    if (kg == 0) {
        float2 bb = *(const float2*)(bias + 2*lane);
        u64 b0 = dup2(bb.x), b1 = dup2(bb.y);
#pragma unroll
        for (int q = 0; q < 4; q++) { acc[q][0] = b0; acc[q][1] = b1; }
    } else {
#pragma unroll
        for (int q = 0; q < 4; q++) { acc[q][0] = 0ull; acc[q][1] = 0ull; }
    }

    const int kbeg = kg * 128;
    const float* w0 = W + kbeg*Dd + 2*lane;
    const float* aP = sA + kbeg*STRA + r0d;

    float2 wb[RD];
#pragma unroll
    for (int q = 0; q < RD; q++) wb[q] = ldg2f(w0 + q*Dd);
    u64 ab[2][4];
#pragma unroll
    for (int q = 0; q < 2; q++) {
        ulonglong2 t0 = *(const ulonglong2*)(aP + q*STRA);
        ulonglong2 t1 = *(const ulonglong2*)(aP + q*STRA + 4);
        ab[q][0] = t0.x; ab[q][1] = t0.y; ab[q][2] = t1.x; ab[q][3] = t1.y;
    }

    int k = 0;
#pragma unroll 8
    for (; k < 128 - RD; k++) {
        const int slot = k & (RD-1), pb = k & 1;
        float2 wf = wb[slot];
        wb[slot] = ldg2f(w0 + (k + RD)*Dd);
        u64 a0 = ab[pb][0], a1 = ab[pb][1], a2 = ab[pb][2], a3 = ab[pb][3];
        {
            const float* ap2 = aP + (k+2)*STRA;
            ulonglong2 t0 = *(const ulonglong2*)(ap2);
            ulonglong2 t1 = *(const ulonglong2*)(ap2 + 4);
            ab[pb][0] = t0.x; ab[pb][1] = t0.y;
            ab[pb][2] = t1.x; ab[pb][3] = t1.y;
        }
        u64 wA = dup2(wf.x), wB = dup2(wf.y);
        fma2(acc[0][0], a0, wA); fma2(acc[0][1], a0, wB);
        fma2(acc[1][0], a1, wA); fma2(acc[1][1], a1, wB);
        fma2(acc[2][0], a2, wA); fma2(acc[2][1], a2, wB);
        fma2(acc[3][0], a3, wA); fma2(acc[3][1], a3, wB);
    }
#pragma unroll
    for (; k < 128; k++) {
        const int slot = k & (RD-1), pb = k & 1;
        float2 wf = wb[slot];
        u64 a0 = ab[pb][0], a1 = ab[pb][1], a2 = ab[pb][2], a3 = ab[pb][3];
        if (k + 2 < 128) {
            const float* ap2 = aP + (k+2)*STRA;
            ulonglong2 t0 = *(const ulonglong2*)(ap2);
            ulonglong2 t1 = *(const ulonglong2*)(ap2 + 4);
            ab[pb][0] = t0.x; ab[pb][1] = t0.y;
            ab[pb][2] = t1.x; ab[pb][3] = t1.y;
        }
        u64 wA = dup2(wf.x), wB = dup2(wf.y);
        fma2(acc[0][0], a0, wA); fma2(acc[0][1], a0, wB);
        fma2(acc[1][0], a1, wA); fma2(acc[1][1], a1, wB);
        fma2(acc[2][0], a2, wA); fma2(acc[2][1], a2, wB);
        fma2(acc[3][0], a3, wA); fma2(acc[3][1], a3, wB);
    }

    const int p = rg*32 + lane;
    if (kg == 1) {
#pragma unroll
        for (int j = 0; j < 4; j++)
            sPart[j*64 + p] = make_ulonglong2(acc[j][0], acc[j][1]);
    }
    __syncthreads();

    if (kg == 0) {
#pragma unroll
        for (int j = 0; j < 4; j++) {
            ulonglong2 t = sPart[j*64 + p];
            acc[j][0] = add2(acc[j][0], t.x);
            acc[j][1] = add2(acc[j][1], t.y);
        }

        const int c0 = 2*lane, c1 = 2*lane + 1;
        // rows r0d..+3 / r0d+4..+7 per column
        float4 v0a = make_float4(lo32(acc[0][0]), hi32(acc[0][0]),
                                 lo32(acc[1][0]), hi32(acc[1][0]));
        float4 v0b = make_float4(lo32(acc[2][0]), hi32(acc[2][0]),
                                 lo32(acc[3][0]), hi32(acc[3][0]));
        float4 v1a = make_float4(lo32(acc[0][1]), hi32(acc[0][1]),
                                 lo32(acc[1][1]), hi32(acc[1][1]));
        float4 v1b = make_float4(lo32(acc[2][1]), hi32(acc[2][1]),
                                 lo32(acc[3][1]), hi32(acc[3][1]));

        if (s < 5) {
            float* kd = sK + s * Dd * STRA;
            float* p0 = kd + c0*STRA + r0d;
            float* p1 = kd + c1*STRA + r0d;
            if ((lane >> 1) & 1) {
                *(float4*)(p1) = v1a; *(float4*)(p1+4) = v1b;
                *(float4*)(p0) = v0a; *(float4*)(p0+4) = v0b;
            } else {
                *(float4*)(p0) = v0a; *(float4*)(p0+4) = v0b;
                *(float4*)(p1) = v1a; *(float4*)(p1+4) = v1b;
            }
        }

        float4 z0a = *(const float4*)(sY + c0*STRY + r0d);
        float4 z0b = *(const float4*)(sY + c0*STRY + r0d + 4);
        float4 z1a = *(const float4*)(sY + c1*STRY + r0d);
        float4 z1b = *(const float4*)(sY + c1*STRY + r0d + 4);
        z0a = f4_fma(cfr, v0a, z0a); z0b = f4_fma(cfr, v0b, z0b);
        z1a = f4_fma(cfr, v1a, z1a); z1b = f4_fma(cfr, v1b, z1b);
#pragma unroll
        for (int l = 0; l < 5; l++) {
            if (l < s) {
                const float* kb = sK + l * Dd * STRA;
                float4 k0a = *(const float4*)(kb + c0*STRA + r0d);
                float4 k0b = *(const float4*)(kb + c0*STRA + r0d + 4);
                float4 k1a = *(const float4*)(kb + c1*STRA + r0d);
                float4 k1b = *(const float4*)(kb + c1*STRA + r0d + 4);
                z0a = f4_fma(cf[l], k0a, z0a); z0b = f4_fma(cf[l], k0b, z0b);
                z1a = f4_fma(cf[l], k1a, z1a); z1b = f4_fma(cf[l], k1b, z1b);
            }
        }
        *(float4*)(sZ + c0*STRA + r0d)     = z0a;
        *(float4*)(sZ + c0*STRA + r0d + 4) = z0b;
        *(float4*)(sZ + c1*STRA + r0d)     = z1a;
        *(float4*)(sZ + c1*STRA + r0d + 4) = z1b;
        if (writeY) {
            *(float4*)(sY + c0*STRY + r0d)     = z0a;
            *(float4*)(sY + c0*STRY + r0d + 4) = z0b;
            *(float4*)(sY + c1*STRY + r0d)     = z1a;
            *(float4*)(sY + c1*STRY + r0d + 4) = z1b;
        }
    }
}

__global__ void __launch_bounds__(NT, 2)
ffjord_kernel(const float* __restrict__ x, float* __restrict__ out, FfjordParams P)
{
    extern __shared__ float sm[];
    float* sZ   = sm;                          // Dd x STRA (no t-row)
    float* sH1  = sZ + Dd * STRA;              // Hh x STRA
    float* sH2  = sH1 + Hh * STRA;             // Hh x STRA
    float* sY   = sH2 + Hh * STRA;             // Dd x STRY
    float* sK   = sY + Dd * STRY;              // [6][Dd][STRA] (slot 5 unused)
    ulonglong2* sPart = (ulonglong2*)(sK + 6 * Dd * STRA);  // 4*64

    const int tid   = threadIdx.x;
    const int lane  = tid & 31;
    const int w     = tid >> 5;
    const int r0    = (w & 1) * 8;             // dense256 rowgroup
    const int g     = w >> 1;                  // dense256 colgroup
    const int rg    = w & 1;                   // dense64 rowgroup
    const int kg    = w >> 1;                  // dense64 K-group
    const int rbase = blockIdx.x * MROWS;

    for (int i = tid; i < MROWS * Dd; i += NT) {
        int r = i >> 6, d = i & 63;
        float v = x[(rbase + r) * Dd + d];
        sY[d * STRY + r] = v;
        sZ[d * STRA + r] = v;
    }
    __syncthreads();

    const float h = 1.0f / 16.0f;

    for (int bij = 0; bij < 2; bij++) {
        const float* W1 = P.W1[bij]; const float* b1 = P.b1[bij];
        const float* W2 = P.W2[bij]; const float* b2 = P.b2[bij];
        const float* W3 = P.W3[bij]; const float* b3 = P.b3[bij];
        const float* W1t = W1 + Dd * Hh;       // time row (row 64)

        for (int step = 0; step < NSTEPS; step++) {
            float t0 = (float)step * h;

            for (int s = 0; s < 6; s++) {
                float tstage = t0 + DP_C[s] * h;

                dense256<Dd, true, true >(W1, b1, W1t, tstage, sZ, sH1,
                                          lane, g, r0);
                __syncthreads();
                dense256<Hh, true, false>(W2, b2, nullptr, 0.f, sH1, sH2,
                                          lane, g, r0);
                __syncthreads();

                float cf[5], cfr;
                bool writeY = (s == 5);
                if (s < 5) {
#pragma unroll
                    for (int l = 0; l < 5; l++) cf[l] = h * DP_A[s+1][l];
                    cfr = h * DP_A[s+1][s];
                } else {
#pragma unroll
                    for (int l = 0; l < 5; l++) cf[l] = h * DP_B[l];
                    cfr = h * DP_B[5];
                }
                dense64_splitk_fused(W3, b3, sH2, sK, sY, sZ, sPart,
                                     cf, cfr, s, writeY, lane, rg, kg);
                __syncthreads();
            }
        }
    }

    for (int i = tid; i < MROWS * Dd; i += NT) {
        int r = i >> 6, d = i & 63;
        out[(rbase + r) * Dd + d] = sY[d * STRY + r];
    }
}

extern "C" void kernel_launch(void* const* d_in, const int* in_sizes, int n_in,
                              void* d_out, int out_size)
{
    (void)in_sizes; (void)n_in; (void)out_size;
    const float* x = (const float*)d_in[0];

    FfjordParams P;
    P.W1[0] = (const float*)d_in[1];  P.b1[0] = (const float*)d_in[2];
    P.W2[0] = (const float*)d_in[3];  P.b2[0] = (const float*)d_in[4];
    P.W3[0] = (const float*)d_in[5];  P.b3[0] = (const float*)d_in[6];
    P.W1[1] = (const float*)d_in[7];  P.b1[1] = (const float*)d_in[8];
    P.W2[1] = (const float*)d_in[9];  P.b2[1] = (const float*)d_in[10];
    P.W3[1] = (const float*)d_in[11]; P.b3[1] = (const float*)d_in[12];

    static_assert(SM_BYTES <= 100 * 1024, "smem budget (2 CTAs/SM)");
    cudaFuncSetAttribute(ffjord_kernel, cudaFuncAttributeMaxDynamicSharedMemorySize, SM_BYTES);

    ffjord_kernel<<<NCTAS, NT, SM_BYTES>>>(x, (float*)d_out, P);
}